// round 14
// baseline (speedup 1.0000x reference)
#include <cuda_runtime.h>
#include <cuda_bf16.h>
#include <cstdint>
#include <cstddef>

// Problem constants
#define BB   128
#define TT   2048
#define UU   256
#define CLS  8        // cluster size (u-split)
#define BPC  8        // batches per cluster
#define UCTA 32       // u per CTA
#define NTHR 256      // 8 warps; warp w owns m-rows [16w,16w+16) = units [4w,4w+4) x 4 gates

#define H_BLOCK_BYTES 1024               // 256 packed words per rank per step
#define TX_BYTES      (CLS*H_BLOCK_BYTES)

typedef unsigned long long ull;

__device__ __forceinline__ uint32_t smem_u32(const void* p) {
    uint32_t a;
    asm("{ .reg .u64 t; cvta.to.shared.u64 t, %1; cvt.u32.u64 %0, t; }" : "=r"(a) : "l"(p));
    return a;
}

__device__ __forceinline__ void mbar_init(uint32_t mbar, uint32_t cnt) {
    asm volatile("mbarrier.init.shared.b64 [%0], %1;" :: "r"(mbar), "r"(cnt) : "memory");
}
__device__ __forceinline__ void mbar_arrive_expect(uint32_t mbar, uint32_t tx) {
    asm volatile("mbarrier.arrive.expect_tx.shared.b64 _, [%0], %1;"
                 :: "r"(mbar), "r"(tx) : "memory");
}
__device__ __forceinline__ void mbar_wait(uint32_t mbar, uint32_t parity) {
    asm volatile(
        "{\n\t.reg .pred P;\n\t"
        "WL_%=:\n\t"
        "mbarrier.try_wait.parity.acquire.cta.shared::cta.b64 P, [%0], %1, 0x989680;\n\t"
        "@P bra.uni WD_%=;\n\t"
        "bra.uni WL_%=;\n\t"
        "WD_%=:\n\t}" :: "r"(mbar), "r"(parity) : "memory");
}

__device__ __forceinline__ void bulk_copy_to_rank(uint32_t dst_local, uint32_t src,
                                                  uint32_t bytes, uint32_t mbar_local,
                                                  uint32_t rank) {
    uint32_t rd, rm;
    asm volatile("mapa.shared::cluster.u32 %0, %1, %2;" : "=r"(rd) : "r"(dst_local), "r"(rank));
    asm volatile("mapa.shared::cluster.u32 %0, %1, %2;" : "=r"(rm) : "r"(mbar_local), "r"(rank));
    asm volatile("cp.async.bulk.shared::cluster.shared::cta.mbarrier::complete_tx::bytes "
                 "[%0], [%1], %2, [%3];"
                 :: "r"(rd), "r"(src), "r"(bytes), "r"(rm) : "memory");
}

__device__ __forceinline__ void mma_bf16(float& d0, float& d1, float& d2, float& d3,
                                         uint32_t a0, uint32_t a1, uint32_t a2, uint32_t a3,
                                         uint32_t b0, uint32_t b1) {
    asm volatile(
        "mma.sync.aligned.m16n8k16.row.col.f32.bf16.bf16.f32 "
        "{%0,%1,%2,%3}, {%4,%5,%6,%7}, {%8,%9}, {%0,%1,%2,%3};"
        : "+f"(d0), "+f"(d1), "+f"(d2), "+f"(d3)
        : "r"(a0), "r"(a1), "r"(a2), "r"(a3), "r"(b0), "r"(b1));
}

__device__ __forceinline__ uint32_t pack_bf16(float lo_elem, float hi_elem) {
    __nv_bfloat162 p = __floats2bfloat162_rn(lo_elem, hi_elem);
    return *(uint32_t*)&p;
}

__device__ __forceinline__ float sigm(float v) { return 1.f / (1.f + __expf(-v)); }
__device__ __forceinline__ float tanh_f(float v) {
    float vv = fminf(fmaxf(v, -15.f), 15.f);
    float e = __expf(-2.f * vv);
    return (1.f - e) / (1.f + e);
}

// B operand word layout (per phase): word = s*128 + hl*64 + (p&3)*16 + n*2 + (p>>2)
// (identical to R12 — validated). Rank r's block = words [r*256, r*256+256).

__global__ void __launch_bounds__(NTHR, 1) __cluster_dims__(CLS, 1, 1)
lstm_hmma_kernel(const float* __restrict__ x,     // [B,T,3]
                 const float* __restrict__ Wx,    // [3,1024]
                 const float* __restrict__ Wh,    // [256,1024]
                 const float* __restrict__ bias,  // [1024]
                 float* __restrict__ out, int out_size)
{
    __shared__ __align__(16) uint32_t bp[2][2048];      // B operand, double-buffered
    __shared__ __align__(16) uint32_t hstage[2][256];   // packed h out-stage
    __shared__ float4 wxs4[3][UCTA];                    // per-unit gate-vector Wx
    __shared__ float4 bis4[UCTA];                       // per-unit gate-vector bias
    __shared__ float xss[2][BPC][4];                    // x double buffer
    __shared__ __align__(8) ull mbars[2];

    const int tid   = threadIdx.x;
    const int wid   = tid >> 5;
    const int lane  = tid & 31;
    const int crank = blockIdx.x & (CLS - 1);
    const int cid   = blockIdx.x >> 3;
    const int bBase = cid * BPC;
    const int uBase = crank * UCTA;

    const uint32_t mbE0 = smem_u32(&mbars[0]);
    const uint32_t mbE1 = mbE0 + 8;

    // ---- Prologue: A = W^T as register fragments, GATE-MINOR rows ----
    // row m = 16*wid + r, r = u_loc*4 + gate -> Wh column = gate*UU + uBase + 4*wid + u_loc
    const int g  = lane >> 2;       // 0..7
    const int tq = lane & 3;
    uint32_t Ahi[64], Alo[64];
    {
        // rows held by this thread: rA = g (u_loc = g>>2, gate = g&3), rB = g+8 (u_loc += 2)
        const int gcolA = (g & 3) * UU + uBase + 4 * wid + (g >> 2);
        const int gcolB = gcolA + 2;
        #pragma unroll
        for (int s = 0; s < 16; ++s) {
            const int k0 = s * 16 + tq * 2;
            float wA0 = Wh[(size_t)(k0)     * 1024 + gcolA];
            float wA1 = Wh[(size_t)(k0 + 1) * 1024 + gcolA];
            float wB0 = Wh[(size_t)(k0)     * 1024 + gcolB];
            float wB1 = Wh[(size_t)(k0 + 1) * 1024 + gcolB];
            float wA8 = Wh[(size_t)(k0 + 8) * 1024 + gcolA];
            float wA9 = Wh[(size_t)(k0 + 9) * 1024 + gcolA];
            float wB8 = Wh[(size_t)(k0 + 8) * 1024 + gcolB];
            float wB9 = Wh[(size_t)(k0 + 9) * 1024 + gcolB];
            uint32_t h0 = pack_bf16(wA0, wA1), h1 = pack_bf16(wB0, wB1);
            uint32_t h2 = pack_bf16(wA8, wA9), h3 = pack_bf16(wB8, wB9);
            Ahi[s * 4 + 0] = h0; Ahi[s * 4 + 1] = h1;
            Ahi[s * 4 + 2] = h2; Ahi[s * 4 + 3] = h3;
            __nv_bfloat162* ph;
            ph = (__nv_bfloat162*)&h0;
            Alo[s * 4 + 0] = pack_bf16(wA0 - __bfloat162float(ph->x), wA1 - __bfloat162float(ph->y));
            ph = (__nv_bfloat162*)&h1;
            Alo[s * 4 + 1] = pack_bf16(wB0 - __bfloat162float(ph->x), wB1 - __bfloat162float(ph->y));
            ph = (__nv_bfloat162*)&h2;
            Alo[s * 4 + 2] = pack_bf16(wA8 - __bfloat162float(ph->x), wA9 - __bfloat162float(ph->y));
            ph = (__nv_bfloat162*)&h3;
            Alo[s * 4 + 3] = pack_bf16(wB8 - __bfloat162float(ph->x), wB9 - __bfloat162float(ph->y));
        }
    }

    // per-unit gate vectors for bias and Wx
    for (int idx = tid; idx < 3 * UCTA; idx += NTHR) {
        int f = idx >> 5, uu2 = idx & 31;
        wxs4[f][uu2] = make_float4(Wx[f * 1024 + 0 * UU + uBase + uu2],
                                   Wx[f * 1024 + 1 * UU + uBase + uu2],
                                   Wx[f * 1024 + 2 * UU + uBase + uu2],
                                   Wx[f * 1024 + 3 * UU + uBase + uu2]);
    }
    if (tid < UCTA)
        bis4[tid] = make_float4(bias[0 * UU + uBase + tid], bias[1 * UU + uBase + tid],
                                bias[2 * UU + uBase + tid], bias[3 * UU + uBase + tid]);
    if (tid < BPC * 3) {
        int xb = tid / 3, xf = tid - xb * 3;
        xss[0][xb][xf] = x[((size_t)(bBase + xb) * TT + 0) * 3 + xf];
    }
    for (int idx = tid; idx < 2 * 2048; idx += NTHR) ((uint32_t*)bp)[idx] = 0u;
    if (tid == 0) {
        mbar_init(mbE0, 1); mbar_init(mbE1, 1);
        mbar_arrive_expect(mbE0, TX_BYTES);
        mbar_arrive_expect(mbE1, TX_BYTES);
    }
    __syncthreads();
    asm volatile("barrier.cluster.arrive.aligned;" ::: "memory");
    asm volatile("barrier.cluster.wait.aligned;"   ::: "memory");

    // ---- Epilogue lane mapping (after in-warp transpose) ----
    const int gamma = (lane >> 2) & 3;          // gate-group position
    const int jj    = (lane >> 4) & 1;
    const int u_loc = jj + 2 * (gamma >> 1);
    const int ebt   = 2 * tq + (gamma & 1);     // batch owned by this lane
    const int uu    = 4 * wid + u_loc;
    const int gu    = uBase + uu;
    const int gb    = bBase + ebt;
    // packing constants (jj==0 lanes pack units (uu, uu+1))
    const int g1     = gamma >> 1;
    const int pv     = (2 * wid + g1) & 7;
    const int pwbase = (wid >> 2) * 128 + (pv & 3) * 16 + ebt * 2 + (pv >> 2);

    const uint32_t bp_s  = smem_u32(&bp[0][0]);
    const uint32_t stg_s = smem_u32(&hstage[0][0]);

    float creg = 0.f, hreg = 0.f;
    uint32_t ph0 = 0, ph1 = 0;
    const unsigned FM = 0xFFFFFFFFu;

    for (int t = 0; t < TT; ++t) {
        const int pp = t & 1;
        const int np = pp ^ 1;

        // all-thread wait on B[pp]; tid0 re-arms
        if (t > 0) {
            uint32_t mb = pp ? mbE1 : mbE0;
            mbar_wait(mb, pp ? ph1 : ph0);
            if (pp) ph1 ^= 1; else ph0 ^= 1;
            if (tid == 0) mbar_arrive_expect(mb, TX_BYTES);
        }

        // prefetch x for step t+1 (LDG early, STS later this step)
        float xv = 0.f;
        if (tid < BPC * 3 && t + 1 < TT)
            xv = x[((size_t)(bBase + tid / 3) * TT + (t + 1)) * 3 + (tid - (tid / 3) * 3)];

        // ---- MMA: 6 independent accumulator chains ----
        float ac[6][4];
        #pragma unroll
        for (int i = 0; i < 6; ++i) {
            ac[i][0] = 0.f; ac[i][1] = 0.f; ac[i][2] = 0.f; ac[i][3] = 0.f;
        }
        {
            const uint32_t* bb = &bp[pp][0];
            const int loff = tq * 16 + g * 2;
            #pragma unroll
            for (int s = 0; s < 16; ++s) {
                ull hp = *(const ull*)(bb + s * 128 + loff);
                ull lp = *(const ull*)(bb + s * 128 + 64 + loff);
                uint32_t bh0 = (uint32_t)hp, bh1 = (uint32_t)(hp >> 32);
                uint32_t bl0 = (uint32_t)lp, bl1 = (uint32_t)(lp >> 32);
                const int si = (s >> 3) * 3;
                mma_bf16(ac[si][0], ac[si][1], ac[si][2], ac[si][3],
                         Ahi[s*4+0], Ahi[s*4+1], Ahi[s*4+2], Ahi[s*4+3], bh0, bh1);
                mma_bf16(ac[si+1][0], ac[si+1][1], ac[si+1][2], ac[si+1][3],
                         Alo[s*4+0], Alo[s*4+1], Alo[s*4+2], Alo[s*4+3], bh0, bh1);
                mma_bf16(ac[si+2][0], ac[si+2][1], ac[si+2][2], ac[si+2][3],
                         Ahi[s*4+0], Ahi[s*4+1], Ahi[s*4+2], Ahi[s*4+3], bl0, bl1);
            }
        }
        float d0 = ac[0][0]+ac[1][0]+ac[2][0]+ac[3][0]+ac[4][0]+ac[5][0];
        float d1 = ac[0][1]+ac[1][1]+ac[2][1]+ac[3][1]+ac[4][1]+ac[5][1];
        float d2 = ac[0][2]+ac[1][2]+ac[2][2]+ac[3][2]+ac[4][2]+ac[5][2];
        float d3 = ac[0][3]+ac[1][3]+ac[2][3]+ac[3][3]+ac[4][3]+ac[5][3];

        // ---- in-warp 4x4 transpose over gate-group dimension (masks 4, 8) ----
        {
            float v;
            v = (lane & 4) ? d0 : d1; v = __shfl_xor_sync(FM, v, 4);
            if (lane & 4) d0 = v; else d1 = v;
            v = (lane & 4) ? d2 : d3; v = __shfl_xor_sync(FM, v, 4);
            if (lane & 4) d2 = v; else d3 = v;
            v = (lane & 8) ? d0 : d2; v = __shfl_xor_sync(FM, v, 8);
            if (lane & 8) d0 = v; else d2 = v;
            v = (lane & 8) ? d1 : d3; v = __shfl_xor_sync(FM, v, 8);
            if (lane & 8) d1 = v; else d3 = v;
        }
        // now: d0=z_i, d1=z_f, d2=z_g, d3=z_o for (unit uu, batch ebt)

        // ---- epilogue (every lane owns one (u,b)) ----
        {
            float4 bv = bis4[uu];
            float4 w0 = wxs4[0][uu], w1 = wxs4[1][uu], w2 = wxs4[2][uu];
            float x0 = xss[pp][ebt][0], x1 = xss[pp][ebt][1], x2 = xss[pp][ebt][2];
            float z0 = d0 + bv.x + x0 * w0.x + x1 * w1.x + x2 * w2.x;
            float z1 = d1 + bv.y + x0 * w0.y + x1 * w1.y + x2 * w2.y;
            float z2 = d2 + bv.z + x0 * w0.z + x1 * w1.z + x2 * w2.z;
            float z3 = d3 + bv.w + x0 * w0.w + x1 * w1.w + x2 * w2.w;
            float ig = sigm(z0);
            float fg = sigm(z1);
            float gv = tanh_f(z2);
            float og = sigm(z3);
            creg = fg * creg + ig * gv;
            hreg = og * tanh_f(creg);
        }

        // stash x prefetch for next step
        if (tid < BPC * 3 && t + 1 < TT)
            xss[np][tid / 3][tid - (tid / 3) * 3] = xv;

        // pack (h[uu], h[uu+1]) into B-fragment words (jj==0 lanes)
        {
            float hn = __shfl_xor_sync(FM, hreg, 16);
            if (jj == 0) {
                uint32_t hiw = pack_bf16(hreg, hn);
                __nv_bfloat162* ph2 = (__nv_bfloat162*)&hiw;
                uint32_t low = pack_bf16(hreg - __bfloat162float(ph2->x),
                                         hn   - __bfloat162float(ph2->y));
                hstage[np][pwbase]      = hiw;
                hstage[np][pwbase + 64] = low;
            }
            out[((size_t)gb * TT + t) * UU + gu] = hreg;
        }
        __syncthreads();   // the ONLY per-step CTA barrier

        // parallel broadcast: warp w's lane 0 -> rank w
        if (lane == 0) {
            asm volatile("fence.proxy.async.shared::cta;" ::: "memory");
            uint32_t src = stg_s + np * H_BLOCK_BYTES;
            uint32_t dst = bp_s + np * 8192 + crank * H_BLOCK_BYTES;
            uint32_t mbn = np ? mbE1 : mbE0;
            bulk_copy_to_rank(dst, src, H_BLOCK_BYTES, mbn, (uint32_t)wid);
        }
    }

    // keep cluster alive until last bulk copies land
    asm volatile("barrier.cluster.arrive.aligned;" ::: "memory");
    asm volatile("barrier.cluster.wait.aligned;"   ::: "memory");

    if (out_size >= BB * TT * UU + 2 * BB * UU) {
        size_t b0 = (size_t)BB * TT * UU;
        out[b0 + (size_t)gb * UU + gu] = hreg;
        out[b0 + (size_t)BB * UU + (size_t)gb * UU + gu] = creg;
    }
}

extern "C" void kernel_launch(void* const* d_in, const int* in_sizes, int n_in,
                              void* d_out, int out_size)
{
    const float* x  = nullptr;  // 786432
    const float* wx = nullptr;  // 3072
    const float* wh = nullptr;  // 262144
    const float* bi = nullptr;  // 1024
    for (int i = 0; i < n_in; ++i) {
        switch (in_sizes[i]) {
            case 786432: x  = (const float*)d_in[i]; break;
            case 3072:   wx = (const float*)d_in[i]; break;
            case 262144: wh = (const float*)d_in[i]; break;
            case 1024:   bi = (const float*)d_in[i]; break;
            default: break;
        }
    }
    if (!x)  x  = (const float*)d_in[0];
    if (!wx) wx = (const float*)d_in[1];
    if (!wh) wh = (const float*)d_in[2];
    if (!bi) bi = (const float*)d_in[3];

    lstm_hmma_kernel<<<BB / BPC * CLS, NTHR>>>(
        x, wx, wh, bi, (float*)d_out, out_size);
}

// round 15
// speedup vs baseline: 1.5460x; 1.5460x over previous
#include <cuda_runtime.h>
#include <cuda_bf16.h>
#include <cstdint>
#include <cstddef>

// Problem constants
#define BB   128
#define TT   2048
#define UU   256
#define CLS  8        // cluster size (u-split)
#define BPC  8        // batches per cluster
#define UCTA 32       // u per CTA
#define NTHR 256      // 8 warps; warp w owns m-rows [16w,16w+16) = units [4w,4w+4) x 4 gates

#define H_BLOCK_BYTES 1024               // 256 packed words per rank per step
#define TX_BYTES      (CLS*H_BLOCK_BYTES)

typedef unsigned long long ull;

__device__ __forceinline__ uint32_t smem_u32(const void* p) {
    uint32_t a;
    asm("{ .reg .u64 t; cvta.to.shared.u64 t, %1; cvt.u32.u64 %0, t; }" : "=r"(a) : "l"(p));
    return a;
}

__device__ __forceinline__ void mbar_init(uint32_t mbar, uint32_t cnt) {
    asm volatile("mbarrier.init.shared.b64 [%0], %1;" :: "r"(mbar), "r"(cnt) : "memory");
}
__device__ __forceinline__ void mbar_arrive_expect(uint32_t mbar, uint32_t tx) {
    asm volatile("mbarrier.arrive.expect_tx.shared.b64 _, [%0], %1;"
                 :: "r"(mbar), "r"(tx) : "memory");
}
__device__ __forceinline__ void mbar_wait(uint32_t mbar, uint32_t parity) {
    asm volatile(
        "{\n\t.reg .pred P;\n\t"
        "WL_%=:\n\t"
        "mbarrier.try_wait.parity.acquire.cta.shared::cta.b64 P, [%0], %1, 0x989680;\n\t"
        "@P bra.uni WD_%=;\n\t"
        "bra.uni WL_%=;\n\t"
        "WD_%=:\n\t}" :: "r"(mbar), "r"(parity) : "memory");
}

__device__ __forceinline__ void bulk_copy_to_rank(uint32_t dst_local, uint32_t src,
                                                  uint32_t bytes, uint32_t mbar_local,
                                                  uint32_t rank) {
    uint32_t rd, rm;
    asm volatile("mapa.shared::cluster.u32 %0, %1, %2;" : "=r"(rd) : "r"(dst_local), "r"(rank));
    asm volatile("mapa.shared::cluster.u32 %0, %1, %2;" : "=r"(rm) : "r"(mbar_local), "r"(rank));
    asm volatile("cp.async.bulk.shared::cluster.shared::cta.mbarrier::complete_tx::bytes "
                 "[%0], [%1], %2, [%3];"
                 :: "r"(rd), "r"(src), "r"(bytes), "r"(rm) : "memory");
}

__device__ __forceinline__ void mma_bf16(float& d0, float& d1, float& d2, float& d3,
                                         uint32_t a0, uint32_t a1, uint32_t a2, uint32_t a3,
                                         uint32_t b0, uint32_t b1) {
    asm volatile(
        "mma.sync.aligned.m16n8k16.row.col.f32.bf16.bf16.f32 "
        "{%0,%1,%2,%3}, {%4,%5,%6,%7}, {%8,%9}, {%0,%1,%2,%3};"
        : "+f"(d0), "+f"(d1), "+f"(d2), "+f"(d3)
        : "r"(a0), "r"(a1), "r"(a2), "r"(a3), "r"(b0), "r"(b1));
}

__device__ __forceinline__ uint32_t pack_bf16(float lo_elem, float hi_elem) {
    __nv_bfloat162 p = __floats2bfloat162_rn(lo_elem, hi_elem);
    return *(uint32_t*)&p;
}

__device__ __forceinline__ float sigm(float v) { return 1.f / (1.f + __expf(-v)); }
__device__ __forceinline__ float tanh_f(float v) {
    float vv = fminf(fmaxf(v, -15.f), 15.f);
    float e = __expf(-2.f * vv);
    return (1.f - e) / (1.f + e);
}

// B operand word layout (per phase): word = s*128 + hl*64 + (p&3)*16 + n*2 + (p>>2)
// (validated in R12). Rank r's block = words [r*256, r*256+256).

__global__ void __launch_bounds__(NTHR, 1) __cluster_dims__(CLS, 1, 1)
lstm_hmma_kernel(const float* __restrict__ x,     // [B,T,3]
                 const float* __restrict__ Wx,    // [3,1024]
                 const float* __restrict__ Wh,    // [256,1024]
                 const float* __restrict__ bias,  // [1024]
                 float* __restrict__ out, int out_size)
{
    __shared__ __align__(16) uint32_t bp[2][2048];      // B operand, double-buffered
    __shared__ __align__(16) uint32_t hstage[2][256];   // packed h out-stage
    __shared__ float4 wxs4[3][UCTA];                    // per-unit gate-vector Wx
    __shared__ float4 bis4[UCTA];                       // per-unit gate-vector bias
    __shared__ float xss[2][BPC][4];                    // x double buffer
    __shared__ __align__(8) ull mbars[2];

    const int tid   = threadIdx.x;
    const int wid   = tid >> 5;
    const int lane  = tid & 31;
    const int crank = blockIdx.x & (CLS - 1);
    const int cid   = blockIdx.x >> 3;
    const int bBase = cid * BPC;
    const int uBase = crank * UCTA;

    const uint32_t mbE0 = smem_u32(&mbars[0]);
    const uint32_t mbE1 = mbE0 + 8;

    // ---- Prologue: A = W^T as register fragments, GATE-MINOR rows ----
    const int g  = lane >> 2;       // 0..7
    const int tq = lane & 3;
    uint32_t Ahi[64], Alo[64];
    {
        const int gcolA = (g & 3) * UU + uBase + 4 * wid + (g >> 2);
        const int gcolB = gcolA + 2;
        #pragma unroll
        for (int s = 0; s < 16; ++s) {
            const int k0 = s * 16 + tq * 2;
            float wA0 = Wh[(size_t)(k0)     * 1024 + gcolA];
            float wA1 = Wh[(size_t)(k0 + 1) * 1024 + gcolA];
            float wB0 = Wh[(size_t)(k0)     * 1024 + gcolB];
            float wB1 = Wh[(size_t)(k0 + 1) * 1024 + gcolB];
            float wA8 = Wh[(size_t)(k0 + 8) * 1024 + gcolA];
            float wA9 = Wh[(size_t)(k0 + 9) * 1024 + gcolA];
            float wB8 = Wh[(size_t)(k0 + 8) * 1024 + gcolB];
            float wB9 = Wh[(size_t)(k0 + 9) * 1024 + gcolB];
            uint32_t h0 = pack_bf16(wA0, wA1), h1 = pack_bf16(wB0, wB1);
            uint32_t h2 = pack_bf16(wA8, wA9), h3 = pack_bf16(wB8, wB9);
            Ahi[s * 4 + 0] = h0; Ahi[s * 4 + 1] = h1;
            Ahi[s * 4 + 2] = h2; Ahi[s * 4 + 3] = h3;
            __nv_bfloat162* ph;
            ph = (__nv_bfloat162*)&h0;
            Alo[s * 4 + 0] = pack_bf16(wA0 - __bfloat162float(ph->x), wA1 - __bfloat162float(ph->y));
            ph = (__nv_bfloat162*)&h1;
            Alo[s * 4 + 1] = pack_bf16(wB0 - __bfloat162float(ph->x), wB1 - __bfloat162float(ph->y));
            ph = (__nv_bfloat162*)&h2;
            Alo[s * 4 + 2] = pack_bf16(wA8 - __bfloat162float(ph->x), wA9 - __bfloat162float(ph->y));
            ph = (__nv_bfloat162*)&h3;
            Alo[s * 4 + 3] = pack_bf16(wB8 - __bfloat162float(ph->x), wB9 - __bfloat162float(ph->y));
        }
    }

    for (int idx = tid; idx < 3 * UCTA; idx += NTHR) {
        int f = idx >> 5, uu2 = idx & 31;
        wxs4[f][uu2] = make_float4(Wx[f * 1024 + 0 * UU + uBase + uu2],
                                   Wx[f * 1024 + 1 * UU + uBase + uu2],
                                   Wx[f * 1024 + 2 * UU + uBase + uu2],
                                   Wx[f * 1024 + 3 * UU + uBase + uu2]);
    }
    if (tid < UCTA)
        bis4[tid] = make_float4(bias[0 * UU + uBase + tid], bias[1 * UU + uBase + tid],
                                bias[2 * UU + uBase + tid], bias[3 * UU + uBase + tid]);
    if (tid < BPC * 3) {
        int xb = tid / 3, xf = tid - xb * 3;
        xss[0][xb][xf] = x[((size_t)(bBase + xb) * TT + 0) * 3 + xf];
    }
    for (int idx = tid; idx < 2 * 2048; idx += NTHR) ((uint32_t*)bp)[idx] = 0u;
    if (tid == 0) {
        mbar_init(mbE0, 1); mbar_init(mbE1, 1);
        mbar_arrive_expect(mbE0, TX_BYTES);
        mbar_arrive_expect(mbE1, TX_BYTES);
    }
    __syncthreads();
    asm volatile("barrier.cluster.arrive.aligned;" ::: "memory");
    asm volatile("barrier.cluster.wait.aligned;"   ::: "memory");

    // ---- Epilogue lane mapping (after in-warp transpose) ----
    const int gamma = (lane >> 2) & 3;
    const int jj    = (lane >> 4) & 1;
    const int u_loc = jj + 2 * (gamma >> 1);
    const int ebt   = 2 * tq + (gamma & 1);
    const int uu    = 4 * wid + u_loc;
    const int gu    = uBase + uu;
    const int gb    = bBase + ebt;
    const int g1     = gamma >> 1;
    const int pv     = (2 * wid + g1) & 7;
    const int pwbase = (wid >> 2) * 128 + (pv & 3) * 16 + ebt * 2 + (pv >> 2);

    const uint32_t bp_s  = smem_u32(&bp[0][0]);
    const uint32_t stg_s = smem_u32(&hstage[0][0]);

    float creg = 0.f, hreg = 0.f;
    uint32_t ph0 = 0, ph1 = 0;
    const unsigned FM = 0xFFFFFFFFu;

    for (int t = 0; t < TT; ++t) {
        const int pp = t & 1;
        const int np = pp ^ 1;

        // tid0-only wait on B[pp] (keeps mbarrier line quiet); bar releases
        if (t > 0) {
            if (tid == 0) {
                uint32_t mb = pp ? mbE1 : mbE0;
                mbar_wait(mb, pp ? ph1 : ph0);
                mbar_arrive_expect(mb, TX_BYTES);
            }
            if (pp) ph1 ^= 1; else ph0 ^= 1;
            __syncthreads();   // bar1: B operand released to all warps
        }

        // prefetch x for step t+1
        float xv = 0.f;
        if (tid < BPC * 3 && t + 1 < TT)
            xv = x[((size_t)(bBase + tid / 3) * TT + (t + 1)) * 3 + (tid - (tid / 3) * 3)];

        // ---- MMA: 6 independent accumulator chains ----
        float ac[6][4];
        #pragma unroll
        for (int i = 0; i < 6; ++i) {
            ac[i][0] = 0.f; ac[i][1] = 0.f; ac[i][2] = 0.f; ac[i][3] = 0.f;
        }
        {
            const uint32_t* bb = &bp[pp][0];
            const int loff = tq * 16 + g * 2;
            #pragma unroll
            for (int s = 0; s < 16; ++s) {
                ull hp = *(const ull*)(bb + s * 128 + loff);
                ull lp = *(const ull*)(bb + s * 128 + 64 + loff);
                uint32_t bh0 = (uint32_t)hp, bh1 = (uint32_t)(hp >> 32);
                uint32_t bl0 = (uint32_t)lp, bl1 = (uint32_t)(lp >> 32);
                const int si = (s >> 3) * 3;
                mma_bf16(ac[si][0], ac[si][1], ac[si][2], ac[si][3],
                         Ahi[s*4+0], Ahi[s*4+1], Ahi[s*4+2], Ahi[s*4+3], bh0, bh1);
                mma_bf16(ac[si+1][0], ac[si+1][1], ac[si+1][2], ac[si+1][3],
                         Alo[s*4+0], Alo[s*4+1], Alo[s*4+2], Alo[s*4+3], bh0, bh1);
                mma_bf16(ac[si+2][0], ac[si+2][1], ac[si+2][2], ac[si+2][3],
                         Ahi[s*4+0], Ahi[s*4+1], Ahi[s*4+2], Ahi[s*4+3], bl0, bl1);
            }
        }
        float d0 = ac[0][0]+ac[1][0]+ac[2][0]+ac[3][0]+ac[4][0]+ac[5][0];
        float d1 = ac[0][1]+ac[1][1]+ac[2][1]+ac[3][1]+ac[4][1]+ac[5][1];
        float d2 = ac[0][2]+ac[1][2]+ac[2][2]+ac[3][2]+ac[4][2]+ac[5][2];
        float d3 = ac[0][3]+ac[1][3]+ac[2][3]+ac[3][3]+ac[4][3]+ac[5][3];

        // ---- in-warp 4x4 transpose over gate-group dimension (masks 4, 8) ----
        {
            float v;
            v = (lane & 4) ? d0 : d1; v = __shfl_xor_sync(FM, v, 4);
            if (lane & 4) d0 = v; else d1 = v;
            v = (lane & 4) ? d2 : d3; v = __shfl_xor_sync(FM, v, 4);
            if (lane & 4) d2 = v; else d3 = v;
            v = (lane & 8) ? d0 : d2; v = __shfl_xor_sync(FM, v, 8);
            if (lane & 8) d0 = v; else d2 = v;
            v = (lane & 8) ? d1 : d3; v = __shfl_xor_sync(FM, v, 8);
            if (lane & 8) d1 = v; else d3 = v;
        }
        // now: d0=z_i, d1=z_f, d2=z_g, d3=z_o for (unit uu, batch ebt)

        // ---- epilogue (every lane owns one (u,b)) ----
        {
            float4 bv = bis4[uu];
            float4 w0 = wxs4[0][uu], w1 = wxs4[1][uu], w2 = wxs4[2][uu];
            float x0 = xss[pp][ebt][0], x1 = xss[pp][ebt][1], x2 = xss[pp][ebt][2];
            float z0 = d0 + bv.x + x0 * w0.x + x1 * w1.x + x2 * w2.x;
            float z1 = d1 + bv.y + x0 * w0.y + x1 * w1.y + x2 * w2.y;
            float z2 = d2 + bv.z + x0 * w0.z + x1 * w1.z + x2 * w2.z;
            float z3 = d3 + bv.w + x0 * w0.w + x1 * w1.w + x2 * w2.w;
            float ig = sigm(z0);
            float fg = sigm(z1);
            float gv = tanh_f(z2);
            float og = sigm(z3);
            creg = fg * creg + ig * gv;
            hreg = og * tanh_f(creg);
        }

        // stash x prefetch for next step
        if (tid < BPC * 3 && t + 1 < TT)
            xss[np][tid / 3][tid - (tid / 3) * 3] = xv;

        // pack (h[uu], h[uu+1]) into B-fragment words (jj==0 lanes)
        {
            float hn = __shfl_xor_sync(FM, hreg, 16);
            if (jj == 0) {
                uint32_t hiw = pack_bf16(hreg, hn);
                __nv_bfloat162* ph2 = (__nv_bfloat162*)&hiw;
                uint32_t low = pack_bf16(hreg - __bfloat162float(ph2->x),
                                         hn   - __bfloat162float(ph2->y));
                hstage[np][pwbase]      = hiw;
                hstage[np][pwbase + 64] = low;
            }
        }
        __syncthreads();   // bar2: hstage + xss staged

        // parallel broadcast: warp w's lane 0 -> rank w
        if (lane == 0) {
            asm volatile("fence.proxy.async.shared::cta;" ::: "memory");
            uint32_t src = stg_s + np * H_BLOCK_BYTES;
            uint32_t dst = bp_s + np * 8192 + crank * H_BLOCK_BYTES;
            uint32_t mbn = np ? mbE1 : mbE0;
            bulk_copy_to_rank(dst, src, H_BLOCK_BYTES, mbn, (uint32_t)wid);
        }

        // out store AFTER copy issue — off the exchange critical path
        out[((size_t)gb * TT + t) * UU + gu] = hreg;
    }

    // keep cluster alive until last bulk copies land
    asm volatile("barrier.cluster.arrive.aligned;" ::: "memory");
    asm volatile("barrier.cluster.wait.aligned;"   ::: "memory");

    if (out_size >= BB * TT * UU + 2 * BB * UU) {
        size_t b0 = (size_t)BB * TT * UU;
        out[b0 + (size_t)gb * UU + gu] = hreg;
        out[b0 + (size_t)BB * UU + (size_t)gb * UU + gu] = creg;
    }
}

extern "C" void kernel_launch(void* const* d_in, const int* in_sizes, int n_in,
                              void* d_out, int out_size)
{
    const float* x  = nullptr;  // 786432
    const float* wx = nullptr;  // 3072
    const float* wh = nullptr;  // 262144
    const float* bi = nullptr;  // 1024
    for (int i = 0; i < n_in; ++i) {
        switch (in_sizes[i]) {
            case 786432: x  = (const float*)d_in[i]; break;
            case 3072:   wx = (const float*)d_in[i]; break;
            case 262144: wh = (const float*)d_in[i]; break;
            case 1024:   bi = (const float*)d_in[i]; break;
            default: break;
        }
    }
    if (!x)  x  = (const float*)d_in[0];
    if (!wx) wx = (const float*)d_in[1];
    if (!wh) wh = (const float*)d_in[2];
    if (!bi) bi = (const float*)d_in[3];

    lstm_hmma_kernel<<<BB / BPC * CLS, NTHR>>>(
        x, wx, wh, bi, (float*)d_out, out_size);
}